// round 5
// baseline (speedup 1.0000x reference)
#include <cuda_runtime.h>
#include <math.h>

typedef unsigned int u32;
typedef unsigned long long u64;

#define BATCH 8
#define NCLS 80
#define A0n 17328
#define A1n 4332
#define A2n 1083
#define TOTA 22743
#define NSC 1819440            // TOTA*80 per batch
#define PRE 400
#define MAXD 100

// ---------------- device scratch (no allocation allowed) ----------------
__device__ float g_x0[8*76*76*256];
__device__ float g_x1[8*38*38*512];
__device__ float g_x2[8*19*19*1024];
__device__ float g_p0[8*76*76*255];
__device__ float g_p1[8*38*38*255];
__device__ float g_p2[8*19*19*255];
__device__ float g_boxes[8*TOTA*4];
__device__ float g_scores[BATCH*NSC];
__device__ u32 g_hist[BATCH*256];
__device__ u64 g_pref[BATCH];
__device__ u32 g_K[BATCH];
__device__ u32 g_cnt[BATCH];
__device__ u64 g_topc[BATCH*PRE];

__constant__ float c_anch[9][2] = {
    {12,16},{19,36},{40,28},{36,75},{76,55},{72,146},{142,110},{192,243},{459,401}};

// Correctly-rounded f32 sigmoid via double exp (robust to fast-math and to
// whichever f32 sigmoid formula the reference backend used).
__device__ __forceinline__ float sigm(float x){
    return (float)(1.0/(1.0+exp(-(double)x)));
}
__device__ __forceinline__ float expf_cr(float x){
    return (float)exp((double)x);
}

// ---------------- reset (graph replays must be deterministic) ----------------
__global__ void reset_kernel(){
    int i = blockIdx.x*256 + threadIdx.x;
    if (i < BATCH*256) g_hist[i] = 0u;
    if (i < BATCH){ g_pref[i]=0ull; g_K[i]=PRE; g_cnt[i]=0u; }
}

// ---------------- conv3x3 + scale/bias + leaky (chunked Kahan) ----------------
// 8x8 pixel tile x 64 out channels per block; thread: 4px x 4co.
template<int LVL>
__global__ __launch_bounds__(256) void conv3_kernel(const float* __restrict__ in,
    const float* __restrict__ w, const float* __restrict__ gamma,
    const float* __restrict__ beta)
{
    constexpr int CIN  = (LVL==0)?128:(LVL==1)?256:512;
    constexpr int COUT = CIN*2;
    constexpr int H    = (LVL==0)?76:(LVL==1)?38:19;
    constexpr int TX   = (H+7)/8;
    float* out = (LVL==0)?(float*)g_x0:(LVL==1)?(float*)g_x1:(float*)g_x2;

    __shared__ float in_s[16][10][11];
    __shared__ float w_s[9][16][64];

    const int tid = threadIdx.x;
    const int b   = blockIdx.z;
    const int co0 = blockIdx.y*64;
    const int ty0 = (blockIdx.x/TX)*8;
    const int tx0 = (blockIdx.x%TX)*8;
    const int pixg = tid & 15;
    const int cog  = tid >> 4;
    const int rp = pixg >> 1;
    const int cb = (pixg & 1)*4;

    float sum[4][4], cmp[4][4];
    #pragma unroll
    for (int j=0;j<4;j++){
        #pragma unroll
        for (int k=0;k<4;k++){ sum[j][k]=0.f; cmp[j][k]=0.f; }
    }

    const float* inb = in + (size_t)b*H*H*CIN;

    for (int ci0=0; ci0<CIN; ci0+=16){
        __syncthreads();
        for (int idx=tid; idx<1600; idx+=256){
            int pix = idx>>4, ci = idx&15;
            int r = pix/10, c = pix - r*10;
            int gy = ty0-1+r, gx = tx0-1+c;
            float v = 0.f;
            if ((unsigned)gy < (unsigned)H && (unsigned)gx < (unsigned)H)
                v = inb[(gy*H+gx)*CIN + ci0 + ci];
            in_s[ci][r][c] = v;
        }
        for (int idx=tid; idx<9*16*64; idx+=256){
            int tap = idx>>10;
            int rem = idx & 1023;
            int ci = rem>>6, co = rem&63;
            w_s[tap][ci][co] = w[(tap*CIN + ci0+ci)*COUT + co0 + co];
        }
        __syncthreads();

        float ch[4][4];
        #pragma unroll
        for (int j=0;j<4;j++){
            #pragma unroll
            for (int k=0;k<4;k++) ch[j][k]=0.f;
        }

        for (int dr=0; dr<3; dr++){
            #pragma unroll
            for (int dc=0; dc<3; dc++){
                #pragma unroll
                for (int ci=0; ci<16; ci++){
                    float4 wv = *reinterpret_cast<const float4*>(&w_s[dr*3+dc][ci][cog*4]);
                    #pragma unroll
                    for (int j=0;j<4;j++){
                        float a = in_s[ci][rp+dr][cb+dc+j];
                        ch[j][0] += a*wv.x;
                        ch[j][1] += a*wv.y;
                        ch[j][2] += a*wv.z;
                        ch[j][3] += a*wv.w;
                    }
                }
            }
        }
        // Kahan fold of the chunk partial into the running sum
        #pragma unroll
        for (int j=0;j<4;j++){
            #pragma unroll
            for (int k=0;k<4;k++){
                float y = ch[j][k] - cmp[j][k];
                float t = sum[j][k] + y;
                cmp[j][k] = (t - sum[j][k]) - y;
                sum[j][k] = t;
            }
        }
    }

    float gm[4], bt[4];
    #pragma unroll
    for (int k=0;k<4;k++){ gm[k]=gamma[co0+cog*4+k]; bt[k]=beta[co0+cog*4+k]; }
    #pragma unroll
    for (int j=0;j<4;j++){
        int gy = ty0+rp, gx = tx0+cb+j;
        if (gy<H && gx<H){
            float4 v;
            float t0 = sum[j][0]*gm[0]+bt[0]; v.x = t0>0.f? t0 : 0.1f*t0;
            float t1 = sum[j][1]*gm[1]+bt[1]; v.y = t1>0.f? t1 : 0.1f*t1;
            float t2 = sum[j][2]*gm[2]+bt[2]; v.z = t2>0.f? t2 : 0.1f*t2;
            float t3 = sum[j][3]*gm[3]+bt[3]; v.w = t3>0.f? t3 : 0.1f*t3;
            *reinterpret_cast<float4*>(&out[((size_t)(b*H*H) + gy*H+gx)*COUT + co0 + cog*4]) = v;
        }
    }
}

// ---------------- 1x1 conv (GEMM 32px x 255co) + bias (chunked Kahan) ----------------
template<int LVL>
__global__ __launch_bounds__(256) void gemm_kernel(const float* __restrict__ w,
                                                   const float* __restrict__ bias)
{
    constexpr int HD = (LVL==0)?256:(LVL==1)?512:1024;
    constexpr int H  = (LVL==0)?76:(LVL==1)?38:19;
    constexpr int NP = BATCH*H*H;
    const float* x = (LVL==0)?(const float*)g_x0:(LVL==1)?(const float*)g_x1:(const float*)g_x2;
    float* out = (LVL==0)?(float*)g_p0:(LVL==1)?(float*)g_p1:(float*)g_p2;

    __shared__ float xs[32][17];
    __shared__ float ws[16][256];
    const int tid = threadIdx.x;
    const int pix0 = blockIdx.x*32;
    const int pixg = tid & 7;
    const int cog  = tid >> 3;

    float sum[4][8], cmp[4][8];
    #pragma unroll
    for (int j=0;j<4;j++){
        #pragma unroll
        for (int k=0;k<8;k++){ sum[j][k]=0.f; cmp[j][k]=0.f; }
    }

    for (int k0=0;k0<HD;k0+=16){
        __syncthreads();
        {
            int idx = tid*2;
            int p = idx>>4, k = idx&15;
            int pix = pix0+p;
            float v0=0.f, v1=0.f;
            if (pix<NP){ const float* px = x + (size_t)pix*HD + k0 + k; v0=px[0]; v1=px[1]; }
            xs[p][k]=v0; xs[p][k+1]=v1;
        }
        #pragma unroll
        for (int j2=0;j2<16;j2++){
            int idx = tid + j2*256;
            int k = idx>>8, co = idx&255;
            ws[k][co] = (co<255)? w[(k0+k)*255+co] : 0.f;
        }
        __syncthreads();

        float ch[4][8];
        #pragma unroll
        for (int j=0;j<4;j++){
            #pragma unroll
            for (int k=0;k<8;k++) ch[j][k]=0.f;
        }
        #pragma unroll
        for (int k=0;k<16;k++){
            float4 w0 = *reinterpret_cast<const float4*>(&ws[k][cog*8]);
            float4 w1 = *reinterpret_cast<const float4*>(&ws[k][cog*8+4]);
            #pragma unroll
            for (int j=0;j<4;j++){
                float a = xs[pixg*4+j][k];
                ch[j][0]+=a*w0.x; ch[j][1]+=a*w0.y; ch[j][2]+=a*w0.z; ch[j][3]+=a*w0.w;
                ch[j][4]+=a*w1.x; ch[j][5]+=a*w1.y; ch[j][6]+=a*w1.z; ch[j][7]+=a*w1.w;
            }
        }
        #pragma unroll
        for (int j=0;j<4;j++){
            #pragma unroll
            for (int k=0;k<8;k++){
                float y = ch[j][k] - cmp[j][k];
                float t = sum[j][k] + y;
                cmp[j][k] = (t - sum[j][k]) - y;
                sum[j][k] = t;
            }
        }
    }
    #pragma unroll
    for (int j=0;j<4;j++){
        int pix = pix0 + pixg*4 + j;
        if (pix<NP){
            float* o = out + (size_t)pix*255;
            #pragma unroll
            for (int k=0;k<8;k++){
                int co = cog*8+k;
                if (co<255) o[co] = sum[j][k] + bias[co];
            }
        }
    }
}

// ---------------- decode ----------------
__device__ __forceinline__ void level_of(int a, int& lvl, int& H, int& loc){
    if (a < A0n){ lvl=0; H=76; loc=a; }
    else if (a < A0n+A1n){ lvl=1; H=38; loc=a-A0n; }
    else { lvl=2; H=19; loc=a-A0n-A1n; }
}

__global__ void box_kernel(){
    int g = blockIdx.x*256 + threadIdx.x;
    if (g >= BATCH*TOTA) return;
    int a = g % TOTA, b = g / TOTA;
    int lvl,H,loc; level_of(a,lvl,H,loc);
    const float* pred = (lvl==0)?(const float*)g_p0:(lvl==1)?(const float*)g_p1:(const float*)g_p2;
    float stride = (lvl==0)?8.f:(lvl==1)?16.f:32.f;
    int cell = loc/3, an = loc - cell*3;
    int gy = cell / H, gx = cell - gy*H;
    const float* p = pred + ((size_t)(b*H*H + cell))*255 + an*85;
    float cx = (sigm(p[0])*1.05f - 0.025f + (float)gx)*stride;
    float cy = (sigm(p[1])*1.05f - 0.025f + (float)gy)*stride;
    float ww = expf_cr(p[2]) * c_anch[lvl*3+an][0];
    float hh = expf_cr(p[3]) * c_anch[lvl*3+an][1];
    float* o = g_boxes + (size_t)g*4;
    o[0]=cx-0.5f*ww; o[1]=cy-0.5f*hh; o[2]=cx+0.5f*ww; o[3]=cy+0.5f*hh;
}

__global__ void score_kernel(){
    long long g = (long long)blockIdx.x*256 + threadIdx.x;
    if (g >= (long long)BATCH*NSC) return;
    int c = (int)(g % NCLS);
    long long rest = g / NCLS;
    int a = (int)(rest % TOTA);
    int b = (int)(rest / TOTA);
    int lvl,H,loc; level_of(a,lvl,H,loc);
    const float* pred = (lvl==0)?(const float*)g_p0:(lvl==1)?(const float*)g_p1:(const float*)g_p2;
    int cell = loc/3, an = loc - cell*3;
    const float* p = pred + ((size_t)(b*H*H + cell))*255 + an*85;
    float so = sigm(p[4]);
    float sc = sigm(p[5+c]);
    float s = so * sc;                 // f32 product of two rounded f32 sigmoids
    if (s < 0.05f) s = 0.f;
    g_scores[(size_t)b*NSC + (size_t)a*NCLS + c] = s;
}

// ---------------- exact top-400: 8-pass radix select on (key<<32)|~idx ----------------
__global__ void hist_kernel(int p){
    __shared__ u32 h[256];
    int t = threadIdx.x;
    h[t]=0u; __syncthreads();
    int b = blockIdx.y;
    int i = blockIdx.x*256 + t;
    if (i < NSC){
        float s = g_scores[(size_t)b*NSC + i];
        u64 k = ((u64)__float_as_uint(s)<<32) | (u32)(~(u32)i);
        bool ok = (p==0) || ((k >> (64-8*p)) == g_pref[b]);
        if (ok){ int by = (int)((k >> (56-8*p)) & 255); atomicAdd(&h[by],1u); }
    }
    __syncthreads();
    if (h[t]) atomicAdd(&g_hist[b*256+t], h[t]);
}

__global__ void scan_kernel(){
    int b = blockIdx.x;
    __syncthreads();
    if (threadIdx.x == 0){
        u32 K = g_K[b]; u32 cum = 0; int t = 0;
        u32* h = &g_hist[b*256];
        for (t=255; t>0; t--){ cum += h[t]; if (cum >= K) break; }
        if (cum < K) cum += h[0];
        g_K[b] = K - (cum - h[t]);
        g_pref[b] = (g_pref[b]<<8) | (u32)t;
    }
    __syncthreads();
    g_hist[b*256+threadIdx.x] = 0u;
}

__global__ void collect_kernel(){
    int b = blockIdx.y;
    int i = blockIdx.x*256 + threadIdx.x;
    if (i >= NSC) return;
    float s = g_scores[(size_t)b*NSC + i];
    u64 k = ((u64)__float_as_uint(s)<<32) | (u32)(~(u32)i);
    if (k >= g_pref[b]){
        u32 pos = atomicAdd(&g_cnt[b], 1u);
        if (pos < PRE) g_topc[b*PRE + pos] = k;
    }
}

// ---------------- sort 400 + greedy NMS + final top-100 ----------------
__global__ __launch_bounds__(512) void nms_kernel(float* __restrict__ out){
    __shared__ u64 sk[PRE];
    __shared__ float ss[PRE], rx0[PRE],ry0[PRE],rx1[PRE],ry1[PRE];
    __shared__ float ox0[PRE],oy0[PRE],ox1[PRE],oy1[PRE],ar[PRE];
    __shared__ int cl[PRE]; __shared__ int keep[PRE];
    __shared__ float fs[PRE];
    int b = blockIdx.x, t = threadIdx.x;
    if (t < PRE) sk[t] = g_topc[b*PRE+t];
    __syncthreads();
    u64 mk = 0; int rank = 0;
    if (t < PRE){ mk = sk[t]; for (int j=0;j<PRE;j++) rank += (sk[j] > mk); }
    __syncthreads();
    if (t < PRE){
        u32 idx = ~(u32)mk;
        float s = __uint_as_float((u32)(mk>>32));
        int a = idx/NCLS, c = idx - a*NCLS;
        const float* bb = &g_boxes[((size_t)b*TOTA + a)*4];
        float off = (float)c * 1216.0f;
        ss[rank]=s; cl[rank]=c;
        float x0=bb[0],y0=bb[1],x1=bb[2],y1=bb[3];
        rx0[rank]=x0; ry0[rank]=y0; rx1[rank]=x1; ry1[rank]=y1;
        float X0=x0+off,Y0=y0+off,X1=x1+off,Y1=y1+off;
        ox0[rank]=X0; oy0[rank]=Y0; ox1[rank]=X1; oy1[rank]=Y1;
        ar[rank]=(X1-X0)*(Y1-Y0);
        keep[rank]=1;
    }
    __syncthreads();
    float jx0=0,jy0=0,jx1=0,jy1=0,ja=0;
    if (t < PRE){ jx0=ox0[t]; jy0=oy0[t]; jx1=ox1[t]; jy1=oy1[t]; ja=ar[t]; }
    for (int i=0;i<PRE;i++){
        __syncthreads();
        if (t < PRE && t > i && keep[i] && ss[i] > 0.f){
            float lx=fmaxf(ox0[i],jx0), ly=fmaxf(oy0[i],jy0);
            float rx=fminf(ox1[i],jx1), ry=fminf(oy1[i],jy1);
            float w=fmaxf(rx-lx,0.f), h=fmaxf(ry-ly,0.f);
            float inter=w*h;
            float iou=inter/(ar[i]+ja-inter+1e-7f);
            if (iou > 0.5f) keep[t]=0;
        }
    }
    __syncthreads();
    if (t < PRE) fs[t] = (keep[t] && ss[t] > 0.f) ? ss[t] : 0.f;
    __syncthreads();
    if (t < PRE){
        float v = fs[t]; int r2 = 0;
        for (int j=0;j<PRE;j++){ float u = fs[j]; r2 += (u>v) || (u==v && j<t); }
        if (r2 < MAXD){
            float* ob = out + ((size_t)b*MAXD + r2)*4;
            ob[0]=rx0[t]; ob[1]=ry0[t]; ob[2]=rx1[t]; ob[3]=ry1[t];
            out[BATCH*MAXD*4 + b*MAXD + r2] = v;
            out[BATCH*MAXD*5 + b*MAXD + r2] = (float)cl[t];
        }
    }
}

// ---------------- host ----------------
extern "C" void kernel_launch(void* const* d_in, const int* in_sizes, int n_in,
                              void* d_out, int out_size) {
    // Two possible input orderings: dict order (f,w3,g,b,w1,b1 per level) vs
    // reference-signature order (f0,f1,f2, then per-level params).
    int idx[18];
    if (in_sizes[1] == 294912){           // dict order: w3_0 follows f0
        int t[18] = {0,6,12, 1,2,3,4,5, 7,8,9,10,11, 13,14,15,16,17};
        for (int i=0;i<18;i++) idx[i]=t[i];
    } else {                              // signature order
        int t[18] = {0,1,2, 3,4,5,6,7, 8,9,10,11,12, 13,14,15,16,17};
        for (int i=0;i<18;i++) idx[i]=t[i];
    }
    const float* f0   = (const float*)d_in[idx[0]];
    const float* f1   = (const float*)d_in[idx[1]];
    const float* f2   = (const float*)d_in[idx[2]];
    const float* w3_0 = (const float*)d_in[idx[3]];
    const float* g0   = (const float*)d_in[idx[4]];
    const float* bt0  = (const float*)d_in[idx[5]];
    const float* w1_0 = (const float*)d_in[idx[6]];
    const float* b1_0 = (const float*)d_in[idx[7]];
    const float* w3_1 = (const float*)d_in[idx[8]];
    const float* g1   = (const float*)d_in[idx[9]];
    const float* bt1  = (const float*)d_in[idx[10]];
    const float* w1_1 = (const float*)d_in[idx[11]];
    const float* b1_1 = (const float*)d_in[idx[12]];
    const float* w3_2 = (const float*)d_in[idx[13]];
    const float* g2   = (const float*)d_in[idx[14]];
    const float* bt2  = (const float*)d_in[idx[15]];
    const float* w1_2 = (const float*)d_in[idx[16]];
    const float* b1_2 = (const float*)d_in[idx[17]];
    float* out = (float*)d_out;

    reset_kernel<<<8,256>>>();

    conv3_kernel<0><<<dim3(100, 4, 8), 256>>>(f0, w3_0, g0, bt0);
    conv3_kernel<1><<<dim3(25,  8, 8), 256>>>(f1, w3_1, g1, bt1);
    conv3_kernel<2><<<dim3(9,  16, 8), 256>>>(f2, w3_2, g2, bt2);

    gemm_kernel<0><<<1444,256>>>(w1_0, b1_0);
    gemm_kernel<1><<<361, 256>>>(w1_1, b1_1);
    gemm_kernel<2><<<91,  256>>>(w1_2, b1_2);

    box_kernel<<<(BATCH*TOTA+255)/256, 256>>>();
    score_kernel<<<(int)(((long long)BATCH*NSC+255)/256), 256>>>();

    int hb = (NSC+255)/256;
    for (int p=0;p<8;p++){
        hist_kernel<<<dim3(hb, BATCH), 256>>>(p);
        scan_kernel<<<BATCH, 256>>>();
    }
    collect_kernel<<<dim3(hb, BATCH), 256>>>();
    nms_kernel<<<BATCH, 512>>>(out);
}